// round 15
// baseline (speedup 1.0000x reference)
#include <cuda_runtime.h>

#define NROWS 50000
#define NB64  782
#define NB128 391
#define XOFF  (NROWS * 64)
#define BW1_OFF (64 * 64 * 64)
#define BW2_OFF (BW1_OFF + 64 * 1024)
#define BW_TOT  (BW2_OFF + 64 * 256)
#define FW_TOT  (5376 * 64)
#define Q 68
#define P2 132
#define K2_GRID 152

typedef unsigned long long u64;
__device__ __forceinline__ u64 pk2(float lo, float hi) {
    u64 r; asm("mov.b64 %0,{%1,%2};" : "=l"(r) : "f"(lo), "f"(hi)); return r;
}
__device__ __forceinline__ void fma2(u64& d, u64 a, u64 b) {
    asm("fma.rn.f32x2 %0,%1,%2,%0;" : "+l"(d) : "l"(a), "l"(b));
}
__device__ __forceinline__ u64 mul2_(u64 a, u64 b) {
    u64 r; asm("mul.rn.f32x2 %0,%1,%2;" : "=l"(r) : "l"(a), "l"(b)); return r;
}
__device__ __forceinline__ void upk2(u64 v, float& lo, float& hi) {
    asm("mov.b64 {%0,%1},%2;" : "=f"(lo), "=f"(hi) : "l"(v));
}

__device__ __align__(16) float g_h [NB64 * 64 * 64];
__device__ __align__(16) float g_h2[NB64 * 64 * 64];
__device__ __align__(16) float g_dh[NB64 * 64 * 64];
__device__ __align__(16) float g_fw[FW_TOT];
__device__ __align__(16) float g_bw[BW_TOT];

#define MM44P(aul, b4) { \
    u64 bb; \
    bb = pk2(b4.x,b4.x); fma2(accp[0][0],aul.x,bb); fma2(accp[1][0],aul.y,bb); \
    bb = pk2(b4.y,b4.y); fma2(accp[0][1],aul.x,bb); fma2(accp[1][1],aul.y,bb); \
    bb = pk2(b4.z,b4.z); fma2(accp[0][2],aul.x,bb); fma2(accp[1][2],aul.y,bb); \
    bb = pk2(b4.w,b4.w); fma2(accp[0][3],aul.x,bb); fma2(accp[1][3],aul.y,bb); }
#define ZACCP  { for (int i_=0;i_<2;i_++) for (int j_=0;j_<4;j_++) accp[i_][j_]=0ULL; }
#define UNPACKP { for (int i_=0;i_<2;i_++) for (int j_=0;j_<4;j_++) upk2(accp[i_][j_], acc[2*i_][j_], acc[2*i_+1][j_]); }

// pure packed GEMM step into p (8 rows x 4 cols)
#define PSTEP(pp, b4) { \
    u64 bb; \
    bb = pk2(b4.x,b4.x); fma2(pp[0][0],a01.x,bb); fma2(pp[1][0],a01.y,bb); fma2(pp[2][0],a23.x,bb); fma2(pp[3][0],a23.y,bb); \
    bb = pk2(b4.y,b4.y); fma2(pp[0][1],a01.x,bb); fma2(pp[1][1],a01.y,bb); fma2(pp[2][1],a23.x,bb); fma2(pp[3][1],a23.y,bb); \
    bb = pk2(b4.z,b4.z); fma2(pp[0][2],a01.x,bb); fma2(pp[1][2],a01.y,bb); fma2(pp[2][2],a23.x,bb); fma2(pp[3][2],a23.y,bb); \
    bb = pk2(b4.w,b4.w); fma2(pp[0][3],a01.x,bb); fma2(pp[1][3],a01.y,bb); fma2(pp[2][3],a23.x,bb); fma2(pp[3][3],a23.y,bb); }
#define ZP(pp)  { for (int i_=0;i_<4;i_++) for (int j_=0;j_<4;j_++) pp[i_][j_]=0ULL; }
#define PFOLD(pp, f) { for (int i_=0;i_<4;i_++) for (int j_=0;j_<4;j_++) fma2(acc[i_][j_], pp[i_][j_], f[i_]); }

// rank-1 direct into acc: acc += (f * a) * b
#define RK1HALF(f, bf) { \
    u64 av0 = mul2_(f[0], a01.x), av1 = mul2_(f[1], a01.y); \
    u64 av2 = mul2_(f[2], a23.x), av3 = mul2_(f[3], a23.y); \
    u64 bb; \
    bb = pk2(bf.x,bf.x); fma2(acc[0][0],av0,bb); fma2(acc[1][0],av1,bb); fma2(acc[2][0],av2,bb); fma2(acc[3][0],av3,bb); \
    bb = pk2(bf.y,bf.y); fma2(acc[0][1],av0,bb); fma2(acc[1][1],av1,bb); fma2(acc[2][1],av2,bb); fma2(acc[3][1],av3,bb); \
    bb = pk2(bf.z,bf.z); fma2(acc[0][2],av0,bb); fma2(acc[1][2],av1,bb); fma2(acc[2][2],av2,bb); fma2(acc[3][2],av3,bb); \
    bb = pk2(bf.w,bf.w); fma2(acc[0][3],av0,bb); fma2(acc[1][3],av1,bb); fma2(acc[2][3],av2,bb); fma2(acc[3][3],av3,bb); }

// ---------------- prep ----------------
__global__ void prep_w(const float* __restrict__ W0, const float* __restrict__ W1,
                       const float* __restrict__ W2) {
    const float C0 = rsqrtf(5376.0f);
    const float C1 = C0 * rsqrtf(3.0f);
    const float C2 = C0 * rsqrtf(5.0f);
    int idx = blockIdx.x * blockDim.x + threadIdx.x;
    if (idx < FW_TOT) {
        int j = idx >> 6, k = idx & 63;
        float v_;
        if (j < 4096) {
            int u = j >> 6, v = j & 63;
            if (u < v)       v_ = C0 * (W0[(u*64+v)*64+k] + W0[(v*64+u)*64+k]);
            else if (u == v) v_ = C0 * W0[(u*64+u)*64+k];
            else             v_ = 0.f;
        } else if (j < 5120) {
            int t = j - 4096, u = t >> 5, v = t & 31;
            v_ = 0.5f * C1 * (W1[(u*32+v)*64+k] + W1[(v*32+u)*64+k]);
        } else {
            int t = j - 5120, u = t >> 4, v = t & 15;
            v_ = 0.5f * C2 * (W2[(u*16+v)*64+k] + W2[(v*16+u)*64+k]);
        }
        g_fw[idx] = v_;
    } else if (idx < FW_TOT + BW_TOT) {
        int i = idx - FW_TOT;
        float v_;
        if (i < BW1_OFF) {
            int w = i & 63, r = i >> 6, k = r >> 6, v = r & 63;
            v_ = C0 * (W0[(v*64+w)*64+k] + W0[(w*64+v)*64+k]);
        } else if (i < BW2_OFF) {
            int t = i - BW1_OFF, w = t & 31, r = t >> 5, k = r >> 5, v = r & 31;
            v_ = C1 * (W1[(v*32+w)*64+k] + W1[(w*32+v)*64+k]);
        } else {
            int t = i - BW2_OFF, w = t & 15, r = t >> 4, k = r >> 4, v = r & 15;
            v_ = C2 * (W2[(v*16+w)*64+k] + W2[(w*16+v)*64+k]);
        }
        g_bw[i] = v_;
    }
}

// ---------------- K1 bodies ----------------
#define K1A_BYTES ((64 * P2 + 2 * 64 * Q) * 4)
#define K1B_BYTES ((176 * Q + 64 * Q + 64 * Q) * 4)
#define K1AB_SMEM (K1B_BYTES > K1A_BYTES ? K1B_BYTES : K1A_BYTES)

__device__ void k1a_body(const float* __restrict__ X, float* sm, int tile) {
    float* xsT = sm;               // [64 c][P2] -> n
    float* Bs  = sm + 64 * P2;     // [2][64][Q]
    const int tid = threadIdx.x, bn = tile * 128;

    for (int i = tid; i < 8192; i += 256) {
        int n = i >> 6, c = i & 63;
        xsT[c * P2 + n] = (bn + n < NROWS) ? X[(size_t)(bn + n) * 240 + c] : 0.f;
    }
    __syncthreads();
    const int cg = tid & 15, rg = tid >> 4;
    const int r0 = rg * 8, c0 = cg * 4;
    u64 acc[4][4];
#pragma unroll
    for (int i = 0; i < 4; i++)
#pragma unroll
        for (int j = 0; j < 4; j++) acc[i][j] = 0ULL;

    for (int u0 = 0; u0 < 64; u0 += 2) {
#pragma unroll
        for (int q = 0; q < 8; ++q) {
            int f = tid + 256 * q;
            int buf = f >> 10, t = (f >> 4) & 63, kp = (f & 15) << 2;
            if (t >= u0 + buf)
                *(float4*)(Bs + buf * 64 * Q + t * Q + kp) =
                    *(const float4*)(g_fw + (size_t)((u0 + buf) * 64 + t) * 64 + kp);
        }
        __syncthreads();
        u64 f0[4];
        {
            ulonglong2 xp = *(const ulonglong2*)(xsT + u0 * P2 + r0);
            ulonglong2 xq = *(const ulonglong2*)(xsT + u0 * P2 + r0 + 4);
            f0[0] = xp.x; f0[1] = xp.y; f0[2] = xq.x; f0[3] = xq.y;
        }
        u64 p1[4][4]; ZP(p1);
        {   // peel v = u0: chunk0 only (chunk1 B rows start at u0+1)
            ulonglong2 a01 = *(const ulonglong2*)(xsT + u0 * P2 + r0);
            ulonglong2 a23 = *(const ulonglong2*)(xsT + u0 * P2 + r0 + 4);
            float4 b0 = *(const float4*)(Bs + u0 * Q + c0);
            RK1HALF(f0, b0);
        }
#pragma unroll 2
        for (int v = u0 + 1; v < 64; ++v) {
            ulonglong2 a01 = *(const ulonglong2*)(xsT + v * P2 + r0);
            ulonglong2 a23 = *(const ulonglong2*)(xsT + v * P2 + r0 + 4);
            float4 b0 = *(const float4*)(Bs + v * Q + c0);
            float4 b1 = *(const float4*)(Bs + 64 * Q + v * Q + c0);
            RK1HALF(f0, b0);
            PSTEP(p1, b1);
        }
        {
            ulonglong2 xp = *(const ulonglong2*)(xsT + (u0 + 1) * P2 + r0);
            ulonglong2 xq = *(const ulonglong2*)(xsT + (u0 + 1) * P2 + r0 + 4);
            u64 f1[4] = {xp.x, xp.y, xq.x, xq.y};
            PFOLD(p1, f1);
        }
        __syncthreads();
    }
    if (bn + r0 < NROWS) {
#pragma unroll
        for (int i2 = 0; i2 < 4; ++i2) {
            float4 va, vb;
            upk2(acc[i2][0], va.x, vb.x); upk2(acc[i2][1], va.y, vb.y);
            upk2(acc[i2][2], va.z, vb.z); upk2(acc[i2][3], va.w, vb.w);
            size_t na = (size_t)(bn + r0 + 2 * i2);
            *(float4*)(g_h + na * 64 + c0) = va;
            *(float4*)(g_h + (na + 1) * 64 + c0) = vb;
        }
    }
}

__device__ void k1b_body(const float* __restrict__ X, float* sm, int tile) {
    float* xsT = sm;               // [176 c][Q] -> n  (X cols 64..239)
    float* AT  = sm + 176 * Q;
    float* Bs  = sm + 240 * Q;
    const int tid = threadIdx.x, bn = tile * 64;

    for (int i = tid; i < 176 * 64; i += 256) {
        int n = i / 176, c = i - n * 176;
        xsT[c * Q + n] = (bn + n < NROWS) ? X[(size_t)(bn + n) * 240 + 64 + c] : 0.f;
    }
    __syncthreads();
    const int cg = tid & 15, rg = tid >> 4, r0 = rg * 4, c0 = cg * 4;
    u64 accp[2][4]; ZACCP;
    float acc[4][4];

    for (int ch = 0; ch < 16; ++ch) {
#pragma unroll
        for (int q = 0; q < 4; ++q) {
            int f = tid + 256 * q, t = f >> 4, kp = (f & 15) << 2;
            *(float4*)(Bs + t * Q + kp) = *(const float4*)(g_fw + (size_t)(4096 + ch * 64 + t) * 64 + kp);
        }
#pragma unroll
        for (int q = 0; q < 16; ++q) {
            int idx = q * 256 + tid, n = idx & 63, t = idx >> 6;
            int j1 = ch * 64 + t, u = j1 >> 5, v = j1 & 31;
            const float* xu_ = xsT + (u * 3) * Q + n;
            const float* xv_ = xsT + (v * 3) * Q + n;
            AT[t * Q + n] = xu_[0] * xv_[0] + xu_[Q] * xv_[Q] + xu_[2 * Q] * xv_[2 * Q];
        }
        __syncthreads();
#pragma unroll 8
        for (int kk = 0; kk < 64; ++kk) {
            ulonglong2 a = *(const ulonglong2*)(AT + kk * Q + r0);
            float4 b = *(const float4*)(Bs + kk * Q + c0);
            MM44P(a, b);
        }
        __syncthreads();
    }
    for (int ch = 0; ch < 4; ++ch) {
#pragma unroll
        for (int q = 0; q < 4; ++q) {
            int f = tid + 256 * q, t = f >> 4, kp = (f & 15) << 2;
            *(float4*)(Bs + t * Q + kp) = *(const float4*)(g_fw + (size_t)(5120 + ch * 64 + t) * 64 + kp);
        }
#pragma unroll
        for (int q = 0; q < 16; ++q) {
            int idx = q * 256 + tid, n = idx & 63, t = idx >> 6;
            int j2 = ch * 64 + t, u = j2 >> 4, v = j2 & 15;
            const float* xu_ = xsT + (96 + u * 5) * Q + n;
            const float* xv_ = xsT + (96 + v * 5) * Q + n;
            float s = xu_[0] * xv_[0] + xu_[Q] * xv_[Q] + xu_[2 * Q] * xv_[2 * Q]
                    + xu_[3 * Q] * xv_[3 * Q] + xu_[4 * Q] * xv_[4 * Q];
            AT[t * Q + n] = s;
        }
        __syncthreads();
#pragma unroll 8
        for (int kk = 0; kk < 64; ++kk) {
            ulonglong2 a = *(const ulonglong2*)(AT + kk * Q + r0);
            float4 b = *(const float4*)(Bs + kk * Q + c0);
            MM44P(a, b);
        }
        __syncthreads();
    }
    UNPACKP;
#pragma unroll
    for (int i = 0; i < 4; ++i) {
        int n = bn + r0 + i;
        if (n < NROWS)
            *(float4*)(g_h2 + (size_t)n * 64 + c0) =
                make_float4(acc[i][0], acc[i][1], acc[i][2], acc[i][3]);
    }
}

// sequential block ranges: a-blocks first, b-blocks backfill the tail
__global__ void __launch_bounds__(256, 2) k1ab_fwd(const float* __restrict__ X) {
    extern __shared__ float sm[];
    if (blockIdx.x < NB128) k1a_body(X, sm, blockIdx.x);
    else                    k1b_body(X, sm, blockIdx.x - NB128);
}

// ---------------- K2: MLP fwd+bwd, PERSISTENT ----------------
#define K2_SMEM ((10 * 64 * Q + 64) * 4)
__global__ void __launch_bounds__(512) k2_mlp(const float* __restrict__ A1, const float* __restrict__ b1,
                                              const float* __restrict__ A2, const float* __restrict__ b2,
                                              const float* __restrict__ A3, const float* __restrict__ b3,
                                              float* __restrict__ Xout) {
    extern __shared__ float sm[];
    float* A1T = sm;
    float* A2T = sm + 64 * Q;
    float* A3T = sm + 2 * 64 * Q;
    float* A1s = sm + 3 * 64 * Q;
    float* A2s = sm + 4 * 64 * Q;
    float* hT  = sm + 5 * 64 * Q;
    float* g1T = sm + 6 * 64 * Q;
    float* d1T = sm + 7 * 64 * Q;
    float* g2T = sm + 8 * 64 * Q;
    float* d2T = sm + 9 * 64 * Q;
    float* s3  = sm + 10 * 64 * Q;
    const int tid = threadIdx.x;

    for (int i = tid; i < 4096; i += 512) {
        int o = i >> 6, c = i & 63;
        float w1 = A1[i], w2 = A2[i], w3 = A3[i];
        A1s[o * Q + c] = w1; A2s[o * Q + c] = w2;
        A1T[c * Q + o] = w1; A2T[c * Q + o] = w2; A3T[c * Q + o] = w3;
    }
    __syncthreads();
    if (tid < 64) {
        float s = 0.f;
        for (int k = 0; k < 64; ++k) s += A3T[tid * Q + k];
        s3[tid] = s;
    }
    __syncthreads();

    const int cg = tid & 15, rg = tid >> 4, o0 = cg * 4, n0 = rg * 2;
    float rb1[4], rb2[4], rb3[4], rs3[4];
#pragma unroll
    for (int j = 0; j < 4; ++j) {
        rb1[j] = b1[o0 + j]; rb2[j] = b2[o0 + j]; rb3[j] = b3[o0 + j];
        rs3[j] = s3[o0 + j];
    }

    u64 accp[4];
    float zlo[4], zhi[4];
#define K2GEMM(SRC, WT) { \
    accp[0] = accp[1] = accp[2] = accp[3] = 0ULL; \
    _Pragma("unroll 8") \
    for (int kk = 0; kk < 64; ++kk) { \
        u64 a = *(const u64*)(SRC + kk * Q + n0); \
        float4 b = *(const float4*)(WT + kk * Q + o0); \
        fma2(accp[0], a, pk2(b.x, b.x)); fma2(accp[1], a, pk2(b.y, b.y)); \
        fma2(accp[2], a, pk2(b.z, b.z)); fma2(accp[3], a, pk2(b.w, b.w)); \
    } \
    _Pragma("unroll") \
    for (int j = 0; j < 4; ++j) upk2(accp[j], zlo[j], zhi[j]); }

    for (int tile = blockIdx.x; tile < NB64; tile += K2_GRID) {
        const int bn = tile * 64;
        for (int i = tid; i < 4096; i += 512) {
            int n = i >> 6, c = i & 63;
            hT[c * Q + n] = (bn + n < NROWS)
                ? g_h[(size_t)(bn + n) * 64 + c] + g_h2[(size_t)(bn + n) * 64 + c] : 0.f;
        }
        __syncthreads();

        K2GEMM(hT, A1T);
#pragma unroll
        for (int j = 0; j < 4; ++j) {
            float za = zlo[j] + rb1[j], zb = zhi[j] + rb1[j];
            float sa = 1.f / (1.f + expf(-za)), sb = 1.f / (1.f + expf(-zb));
            *(float2*)(g1T + (o0 + j) * Q + n0) = make_float2(za * sa, zb * sb);
            *(float2*)(d1T + (o0 + j) * Q + n0) =
                make_float2(sa * (1.f + za * (1.f - sa)), sb * (1.f + zb * (1.f - sb)));
        }
        __syncthreads();
        K2GEMM(g1T, A2T);
#pragma unroll
        for (int j = 0; j < 4; ++j) {
            float za = zlo[j] + rb2[j], zb = zhi[j] + rb2[j];
            float sa = 1.f / (1.f + expf(-za)), sb = 1.f / (1.f + expf(-zb));
            *(float2*)(g2T + (o0 + j) * Q + n0) = make_float2(za * sa, zb * sb);
            *(float2*)(d2T + (o0 + j) * Q + n0) =
                make_float2(rs3[j] * sa * (1.f + za * (1.f - sa)),
                            rs3[j] * sb * (1.f + zb * (1.f - sb)));
        }
        __syncthreads();
        K2GEMM(g2T, A3T);
        if (bn + n0 < NROWS) {
            float4 va = make_float4(zlo[0] + rb3[0], zlo[1] + rb3[1], zlo[2] + rb3[2], zlo[3] + rb3[3]);
            float4 vb = make_float4(zhi[0] + rb3[0], zhi[1] + rb3[1], zhi[2] + rb3[2], zhi[3] + rb3[3]);
            *(float4*)(Xout + (size_t)(bn + n0) * 64 + o0) = va;
            *(float4*)(Xout + (size_t)(bn + n0 + 1) * 64 + o0) = vb;
        }
        K2GEMM(d2T, A2s);
        __syncthreads();
#pragma unroll
        for (int j = 0; j < 4; ++j) {
            float2 d = *(const float2*)(d1T + (o0 + j) * Q + n0);
            *(float2*)(g1T + (o0 + j) * Q + n0) = make_float2(zlo[j] * d.x, zhi[j] * d.y);
        }
        __syncthreads();
        K2GEMM(g1T, A1s);
        if (bn + n0 < NROWS) {
            *(float4*)(g_dh + (size_t)(bn + n0) * 64 + o0) = make_float4(zlo[0], zlo[1], zlo[2], zlo[3]);
            *(float4*)(g_dh + (size_t)(bn + n0 + 1) * 64 + o0) = make_float4(zhi[0], zhi[1], zhi[2], zhi[3]);
        }
        __syncthreads();
    }
#undef K2GEMM
}

// ---------------- K3 bodies ----------------
#define K3A_BYTES ((2 * 64 * P2 + 2 * 64 * Q) * 4)
#define K3B_BYTES ((176 * Q + 64 * Q + 64 * Q + 64 * Q) * 4)
#define K3AB_SMEM (K3A_BYTES > K3B_BYTES ? K3A_BYTES : K3B_BYTES)

__device__ void k3a_body(const float* __restrict__ X, float* __restrict__ out,
                         float* sm, int tile) {
    float* xsT = sm;                 // [64 v][P2] -> n
    float* dhT = sm + 64 * P2;       // [64 k][P2] -> n
    float* Bs  = sm + 128 * P2;      // [2][64][Q]
    const int tid = threadIdx.x, bn = tile * 128;

    for (int i = tid; i < 8192; i += 256) {
        int n = i >> 6, c = i & 63;
        bool ok = (bn + n) < NROWS;
        xsT[c * P2 + n] = ok ? X[(size_t)(bn + n) * 240 + c] : 0.f;
        dhT[c * P2 + n] = ok ? g_dh[(size_t)(bn + n) * 64 + c] : 0.f;
    }
    __syncthreads();
    const int cg = tid & 15, rg = tid >> 4;
    const int r0 = rg * 8, c0 = cg * 4;
    u64 acc[4][4];
#pragma unroll
    for (int i = 0; i < 4; i++)
#pragma unroll
        for (int j = 0; j < 4; j++) acc[i][j] = 0ULL;

    for (int ch0 = 0; ch0 < 64; ch0 += 2) {
#pragma unroll
        for (int q = 0; q < 8; ++q) {
            int f = tid + 256 * q;
            int buf = f >> 10, t = (f >> 4) & 63, kp = (f & 15) << 2;
            *(float4*)(Bs + buf * 64 * Q + t * Q + kp) =
                *(const float4*)(g_bw + (size_t)((ch0 + buf) * 64 + t) * 64 + kp);
        }
        __syncthreads();
        u64 f0[4];
        {
            ulonglong2 dp = *(const ulonglong2*)(dhT + ch0 * P2 + r0);
            ulonglong2 dq = *(const ulonglong2*)(dhT + ch0 * P2 + r0 + 4);
            f0[0] = dp.x; f0[1] = dp.y; f0[2] = dq.x; f0[3] = dq.y;
        }
        u64 p1[4][4]; ZP(p1);
#pragma unroll 2
        for (int v = 0; v < 64; ++v) {
            ulonglong2 a01 = *(const ulonglong2*)(xsT + v * P2 + r0);
            ulonglong2 a23 = *(const ulonglong2*)(xsT + v * P2 + r0 + 4);
            float4 b0 = *(const float4*)(Bs + v * Q + c0);
            float4 b1 = *(const float4*)(Bs + 64 * Q + v * Q + c0);
            RK1HALF(f0, b0);
            PSTEP(p1, b1);
        }
        {
            ulonglong2 dp = *(const ulonglong2*)(dhT + (ch0 + 1) * P2 + r0);
            ulonglong2 dq = *(const ulonglong2*)(dhT + (ch0 + 1) * P2 + r0 + 4);
            u64 f1[4] = {dp.x, dp.y, dq.x, dq.y};
            PFOLD(p1, f1);
        }
        __syncthreads();
    }
    if (bn + r0 < NROWS) {
#pragma unroll
        for (int i2 = 0; i2 < 4; ++i2) {
            float4 va, vb;
            upk2(acc[i2][0], va.x, vb.x); upk2(acc[i2][1], va.y, vb.y);
            upk2(acc[i2][2], va.z, vb.z); upk2(acc[i2][3], va.w, vb.w);
            size_t na = (size_t)(bn + r0 + 2 * i2);
            *(float4*)(out + XOFF + na * 240 + c0) = va;
            *(float4*)(out + XOFF + (na + 1) * 240 + c0) = vb;
        }
    }
}

__device__ void k3b_body(const float* __restrict__ X, float* __restrict__ out,
                         float* sm, int tile) {
    float* xsT = sm;
    float* dhT = sm + 176 * Q;
    float* Bs  = sm + 240 * Q;
    float* Gs  = sm + 304 * Q;
    const int tid = threadIdx.x, bn = tile * 64;

    for (int i = tid; i < 176 * 64; i += 256) {
        int n = i / 176, c = i - n * 176;
        xsT[c * Q + n] = (bn + n < NROWS) ? X[(size_t)(bn + n) * 240 + 64 + c] : 0.f;
    }
    for (int i = tid; i < 4096; i += 256) {
        int n = i >> 6, c = i & 63;
        dhT[c * Q + n] = (bn + n < NROWS) ? g_dh[(size_t)(bn + n) * 64 + c] : 0.f;
    }
    __syncthreads();
    const int cg = tid & 15, rg = tid >> 4, r0 = rg * 4, c0 = cg * 4;
    const int an = tid & 63, ag = tid >> 6;
    u64 accp[2][4];
    float acc[4][4];

    {
        float y1[8][3];
#pragma unroll
        for (int a = 0; a < 8; a++)
#pragma unroll
            for (int m = 0; m < 3; m++) y1[a][m] = 0.f;
        for (int ch = 0; ch < 16; ++ch) {
#pragma unroll
            for (int q = 0; q < 4; ++q) {
                int f = tid + 256 * q, t = f >> 4, wp = (f & 15) << 2;
                *(float4*)(Bs + t * Q + wp) =
                    *(const float4*)(g_bw + BW1_OFF + (size_t)t * 1024 + ch * 64 + wp);
            }
            __syncthreads();
            ZACCP;
#pragma unroll 8
            for (int kk = 0; kk < 64; ++kk) {
                ulonglong2 a = *(const ulonglong2*)(dhT + kk * Q + r0);
                float4 b = *(const float4*)(Bs + kk * Q + c0);
                MM44P(a, b);
            }
            UNPACKP;
#pragma unroll
            for (int j = 0; j < 4; ++j)
                *(float4*)(Gs + (c0 + j) * Q + r0) =
                    make_float4(acc[0][j], acc[1][j], acc[2][j], acc[3][j]);
            __syncthreads();
            float xa[3], xb[3];
#pragma unroll
            for (int m = 0; m < 3; m++) {
                xa[m] = xsT[((2 * ch) * 3 + m) * Q + an];
                xb[m] = xsT[((2 * ch + 1) * 3 + m) * Q + an];
            }
#pragma unroll
            for (int ww = 0; ww < 8; ++ww) {
                int w = ag * 8 + ww;
                float g0 = Gs[w * Q + an];
                float g1 = Gs[(32 + w) * Q + an];
#pragma unroll
                for (int m = 0; m < 3; m++) y1[ww][m] += g0 * xa[m] + g1 * xb[m];
            }
            __syncthreads();
        }
        if (bn + an < NROWS) {
#pragma unroll
            for (int ww = 0; ww < 8; ++ww)
#pragma unroll
                for (int m = 0; m < 3; m++)
                    out[XOFF + (size_t)(bn + an) * 240 + 64 + (ag * 8 + ww) * 3 + m] = y1[ww][m];
        }
    }
    {
        float y2[4][5];
#pragma unroll
        for (int a = 0; a < 4; a++)
#pragma unroll
            for (int m = 0; m < 5; m++) y2[a][m] = 0.f;
        for (int ch = 0; ch < 4; ++ch) {
#pragma unroll
            for (int q = 0; q < 4; ++q) {
                int f = tid + 256 * q, t = f >> 4, wp = (f & 15) << 2;
                *(float4*)(Bs + t * Q + wp) =
                    *(const float4*)(g_bw + BW2_OFF + (size_t)t * 256 + ch * 64 + wp);
            }
            __syncthreads();
            ZACCP;
#pragma unroll 8
            for (int kk = 0; kk < 64; ++kk) {
                ulonglong2 a = *(const ulonglong2*)(dhT + kk * Q + r0);
                float4 b = *(const float4*)(Bs + kk * Q + c0);
                MM44P(a, b);
            }
            UNPACKP;
#pragma unroll
            for (int j = 0; j < 4; ++j)
                *(float4*)(Gs + (c0 + j) * Q + r0) =
                    make_float4(acc[0][j], acc[1][j], acc[2][j], acc[3][j]);
            __syncthreads();
            float xv[4][5];
#pragma unroll
            for (int vv = 0; vv < 4; vv++)
#pragma unroll
                for (int m = 0; m < 5; m++)
                    xv[vv][m] = xsT[(96 + (4 * ch + vv) * 5 + m) * Q + an];
#pragma unroll
            for (int ww = 0; ww < 4; ++ww) {
                int w = ag * 4 + ww;
#pragma unroll
                for (int vv = 0; vv < 4; vv++) {
                    float g = Gs[(vv * 16 + w) * Q + an];
#pragma unroll
                    for (int m = 0; m < 5; m++) y2[ww][m] += g * xv[vv][m];
                }
            }
            __syncthreads();
        }
        if (bn + an < NROWS) {
#pragma unroll
            for (int ww = 0; ww < 4; ++ww)
#pragma unroll
                for (int m = 0; m < 5; m++)
                    out[XOFF + (size_t)(bn + an) * 240 + 160 + (ag * 4 + ww) * 5 + m] = y2[ww][m];
        }
    }
}

__global__ void __launch_bounds__(256, 2) k3ab_bwd(const float* __restrict__ X,
                                                   float* __restrict__ out) {
    extern __shared__ float sm[];
    if (blockIdx.x < NB128) k3a_body(X, out, sm, blockIdx.x);
    else                    k3b_body(X, out, sm, blockIdx.x - NB128);
}

// ---------------- launch ----------------
extern "C" void kernel_launch(void* const* d_in, const int* in_sizes, int n_in,
                              void* d_out, int out_size) {
    const float* X  = (const float*)d_in[0];
    const float* W0 = (const float*)d_in[1];
    const float* W1 = (const float*)d_in[2];
    const float* W2 = (const float*)d_in[3];
    const float* A1 = (const float*)d_in[4];
    const float* b1 = (const float*)d_in[5];
    const float* A2 = (const float*)d_in[6];
    const float* b2 = (const float*)d_in[7];
    const float* A3 = (const float*)d_in[8];
    const float* b3 = (const float*)d_in[9];
    float* out = (float*)d_out;

    cudaFuncSetAttribute(k1ab_fwd, cudaFuncAttributeMaxDynamicSharedMemorySize, K1AB_SMEM);
    cudaFuncSetAttribute(k2_mlp,   cudaFuncAttributeMaxDynamicSharedMemorySize, K2_SMEM);
    cudaFuncSetAttribute(k3ab_bwd, cudaFuncAttributeMaxDynamicSharedMemorySize, K3AB_SMEM);

    prep_w<<<(FW_TOT + BW_TOT + 255) / 256, 256>>>(W0, W1, W2);
    k1ab_fwd<<<NB128 + NB64, 256, K1AB_SMEM>>>(X);
    k2_mlp<<<K2_GRID, 512, K2_SMEM>>>(A1, b1, A2, b2, A3, b3, out);
    k3ab_bwd<<<NB128 + NB64, 256, K3AB_SMEM>>>(X, out);
}

// round 16
// speedup vs baseline: 1.0371x; 1.0371x over previous
#include <cuda_runtime.h>

#define NROWS 50000
#define NB64  782
#define NB128 391
#define XOFF  (NROWS * 64)
#define BW1_OFF (64 * 64 * 64)
#define BW2_OFF (BW1_OFF + 64 * 1024)
#define BW_TOT  (BW2_OFF + 64 * 256)
#define FW_TOT  (5376 * 64)
#define Q 68
#define P2 132
#define K2_GRID 152

typedef unsigned long long u64;
__device__ __forceinline__ u64 pk2(float lo, float hi) {
    u64 r; asm("mov.b64 %0,{%1,%2};" : "=l"(r) : "f"(lo), "f"(hi)); return r;
}
__device__ __forceinline__ void fma2(u64& d, u64 a, u64 b) {
    asm("fma.rn.f32x2 %0,%1,%2,%0;" : "+l"(d) : "l"(a), "l"(b));
}
__device__ __forceinline__ void upk2(u64 v, float& lo, float& hi) {
    asm("mov.b64 {%0,%1},%2;" : "=f"(lo), "=f"(hi) : "l"(v));
}

__device__ __align__(16) float g_h [NB64 * 64 * 64];
__device__ __align__(16) float g_h2[NB64 * 64 * 64];
__device__ __align__(16) float g_dh[NB64 * 64 * 64];
__device__ __align__(16) float g_fw[FW_TOT];
__device__ __align__(16) float g_bw[BW_TOT];

#define MM44P(aul, b4) { \
    u64 bb; \
    bb = pk2(b4.x,b4.x); fma2(accp[0][0],aul.x,bb); fma2(accp[1][0],aul.y,bb); \
    bb = pk2(b4.y,b4.y); fma2(accp[0][1],aul.x,bb); fma2(accp[1][1],aul.y,bb); \
    bb = pk2(b4.z,b4.z); fma2(accp[0][2],aul.x,bb); fma2(accp[1][2],aul.y,bb); \
    bb = pk2(b4.w,b4.w); fma2(accp[0][3],aul.x,bb); fma2(accp[1][3],aul.y,bb); }
#define ZACCP  { for (int i_=0;i_<2;i_++) for (int j_=0;j_<4;j_++) accp[i_][j_]=0ULL; }
#define UNPACKP { for (int i_=0;i_<2;i_++) for (int j_=0;j_<4;j_++) upk2(accp[i_][j_], acc[2*i_][j_], acc[2*i_+1][j_]); }

// pure packed GEMM step into p (8 rows x 4 cols)
#define PSTEP(pp, b4) { \
    u64 bb; \
    bb = pk2(b4.x,b4.x); fma2(pp[0][0],a01.x,bb); fma2(pp[1][0],a01.y,bb); fma2(pp[2][0],a23.x,bb); fma2(pp[3][0],a23.y,bb); \
    bb = pk2(b4.y,b4.y); fma2(pp[0][1],a01.x,bb); fma2(pp[1][1],a01.y,bb); fma2(pp[2][1],a23.x,bb); fma2(pp[3][1],a23.y,bb); \
    bb = pk2(b4.z,b4.z); fma2(pp[0][2],a01.x,bb); fma2(pp[1][2],a01.y,bb); fma2(pp[2][2],a23.x,bb); fma2(pp[3][2],a23.y,bb); \
    bb = pk2(b4.w,b4.w); fma2(pp[0][3],a01.x,bb); fma2(pp[1][3],a01.y,bb); fma2(pp[2][3],a23.x,bb); fma2(pp[3][3],a23.y,bb); }
#define ZP(pp)  { for (int i_=0;i_<4;i_++) for (int j_=0;j_<4;j_++) pp[i_][j_]=0ULL; }
#define PFOLD(pp, f) { for (int i_=0;i_<4;i_++) for (int j_=0;j_<4;j_++) fma2(acc[i_][j_], pp[i_][j_], f[i_]); }

// ---------------- prep ----------------
__global__ void prep_w(const float* __restrict__ W0, const float* __restrict__ W1,
                       const float* __restrict__ W2) {
    const float C0 = rsqrtf(5376.0f);
    const float C1 = C0 * rsqrtf(3.0f);
    const float C2 = C0 * rsqrtf(5.0f);
    int idx = blockIdx.x * blockDim.x + threadIdx.x;
    if (idx < FW_TOT) {
        int j = idx >> 6, k = idx & 63;
        float v_;
        if (j < 4096) {
            int u = j >> 6, v = j & 63;
            if (u < v)       v_ = C0 * (W0[(u*64+v)*64+k] + W0[(v*64+u)*64+k]);
            else if (u == v) v_ = C0 * W0[(u*64+u)*64+k];
            else             v_ = 0.f;
        } else if (j < 5120) {
            int t = j - 4096, u = t >> 5, v = t & 31;
            v_ = 0.5f * C1 * (W1[(u*32+v)*64+k] + W1[(v*32+u)*64+k]);
        } else {
            int t = j - 5120, u = t >> 4, v = t & 15;
            v_ = 0.5f * C2 * (W2[(u*16+v)*64+k] + W2[(v*16+u)*64+k]);
        }
        g_fw[idx] = v_;
    } else if (idx < FW_TOT + BW_TOT) {
        int i = idx - FW_TOT;
        float v_;
        if (i < BW1_OFF) {
            int w = i & 63, r = i >> 6, k = r >> 6, v = r & 63;
            v_ = C0 * (W0[(v*64+w)*64+k] + W0[(w*64+v)*64+k]);
        } else if (i < BW2_OFF) {
            int t = i - BW1_OFF, w = t & 31, r = t >> 5, k = r >> 5, v = r & 31;
            v_ = C1 * (W1[(v*32+w)*64+k] + W1[(w*32+v)*64+k]);
        } else {
            int t = i - BW2_OFF, w = t & 15, r = t >> 4, k = r >> 4, v = r & 15;
            v_ = C2 * (W2[(v*16+w)*64+k] + W2[(w*16+v)*64+k]);
        }
        g_bw[i] = v_;
    }
}

// ---------------- K1 bodies (R14-proven) ----------------
#define K1A_BYTES ((64 * P2 + 2 * 64 * Q) * 4)
#define K1B_BYTES ((176 * Q + 64 * Q + 64 * Q) * 4)
#define K1AB_SMEM (K1B_BYTES > K1A_BYTES ? K1B_BYTES : K1A_BYTES)

__device__ void k1a_body(const float* __restrict__ X, float* sm, int tile) {
    float* xsT = sm;               // [64 c][P2] -> n
    float* Bs  = sm + 64 * P2;     // [2][64][Q]
    const int tid = threadIdx.x, bn = tile * 128;

    for (int i = tid; i < 8192; i += 256) {
        int n = i >> 6, c = i & 63;
        xsT[c * P2 + n] = (bn + n < NROWS) ? X[(size_t)(bn + n) * 240 + c] : 0.f;
    }
    __syncthreads();
    const int cg = tid & 15, rg = tid >> 4;
    const int r0 = rg * 8, c0 = cg * 4;
    u64 acc[4][4];
#pragma unroll
    for (int i = 0; i < 4; i++)
#pragma unroll
        for (int j = 0; j < 4; j++) acc[i][j] = 0ULL;

    for (int u0 = 0; u0 < 64; u0 += 2) {
#pragma unroll
        for (int q = 0; q < 8; ++q) {
            int f = tid + 256 * q;
            int buf = f >> 10, t = (f >> 4) & 63, kp = (f & 15) << 2;
            if (t >= u0 + buf)
                *(float4*)(Bs + buf * 64 * Q + t * Q + kp) =
                    *(const float4*)(g_fw + (size_t)((u0 + buf) * 64 + t) * 64 + kp);
        }
        __syncthreads();
        {
            u64 p[4][4]; ZP(p);
#pragma unroll 4
            for (int v = u0; v < 64; ++v) {
                ulonglong2 a01 = *(const ulonglong2*)(xsT + v * P2 + r0);
                ulonglong2 a23 = *(const ulonglong2*)(xsT + v * P2 + r0 + 4);
                float4 b = *(const float4*)(Bs + v * Q + c0);
                PSTEP(p, b);
            }
            ulonglong2 xp = *(const ulonglong2*)(xsT + u0 * P2 + r0);
            ulonglong2 xq = *(const ulonglong2*)(xsT + u0 * P2 + r0 + 4);
            u64 f0[4] = {xp.x, xp.y, xq.x, xq.y};
            PFOLD(p, f0);
        }
        {
            u64 p[4][4]; ZP(p);
#pragma unroll 4
            for (int v = u0 + 1; v < 64; ++v) {
                ulonglong2 a01 = *(const ulonglong2*)(xsT + v * P2 + r0);
                ulonglong2 a23 = *(const ulonglong2*)(xsT + v * P2 + r0 + 4);
                float4 b = *(const float4*)(Bs + 64 * Q + v * Q + c0);
                PSTEP(p, b);
            }
            ulonglong2 xp = *(const ulonglong2*)(xsT + (u0 + 1) * P2 + r0);
            ulonglong2 xq = *(const ulonglong2*)(xsT + (u0 + 1) * P2 + r0 + 4);
            u64 f1[4] = {xp.x, xp.y, xq.x, xq.y};
            PFOLD(p, f1);
        }
        __syncthreads();
    }
    if (bn + r0 < NROWS) {
#pragma unroll
        for (int i2 = 0; i2 < 4; ++i2) {
            float4 va, vb;
            upk2(acc[i2][0], va.x, vb.x); upk2(acc[i2][1], va.y, vb.y);
            upk2(acc[i2][2], va.z, vb.z); upk2(acc[i2][3], va.w, vb.w);
            size_t na = (size_t)(bn + r0 + 2 * i2);
            *(float4*)(g_h + na * 64 + c0) = va;
            *(float4*)(g_h + (na + 1) * 64 + c0) = vb;
        }
    }
}

__device__ void k1b_body(const float* __restrict__ X, float* sm, int tile) {
    float* xsT = sm;               // [176 c][Q] -> n  (X cols 64..239)
    float* AT  = sm + 176 * Q;
    float* Bs  = sm + 240 * Q;
    const int tid = threadIdx.x, bn = tile * 64;

    for (int i = tid; i < 176 * 64; i += 256) {
        int n = i / 176, c = i - n * 176;
        xsT[c * Q + n] = (bn + n < NROWS) ? X[(size_t)(bn + n) * 240 + 64 + c] : 0.f;
    }
    __syncthreads();
    const int cg = tid & 15, rg = tid >> 4, r0 = rg * 4, c0 = cg * 4;
    u64 accp[2][4]; ZACCP;
    float acc[4][4];

    for (int ch = 0; ch < 16; ++ch) {
#pragma unroll
        for (int q = 0; q < 4; ++q) {
            int f = tid + 256 * q, t = f >> 4, kp = (f & 15) << 2;
            *(float4*)(Bs + t * Q + kp) = *(const float4*)(g_fw + (size_t)(4096 + ch * 64 + t) * 64 + kp);
        }
#pragma unroll
        for (int q = 0; q < 16; ++q) {
            int idx = q * 256 + tid, n = idx & 63, t = idx >> 6;
            int j1 = ch * 64 + t, u = j1 >> 5, v = j1 & 31;
            const float* xu_ = xsT + (u * 3) * Q + n;
            const float* xv_ = xsT + (v * 3) * Q + n;
            AT[t * Q + n] = xu_[0] * xv_[0] + xu_[Q] * xv_[Q] + xu_[2 * Q] * xv_[2 * Q];
        }
        __syncthreads();
#pragma unroll 8
        for (int kk = 0; kk < 64; ++kk) {
            ulonglong2 a = *(const ulonglong2*)(AT + kk * Q + r0);
            float4 b = *(const float4*)(Bs + kk * Q + c0);
            MM44P(a, b);
        }
        __syncthreads();
    }
    for (int ch = 0; ch < 4; ++ch) {
#pragma unroll
        for (int q = 0; q < 4; ++q) {
            int f = tid + 256 * q, t = f >> 4, kp = (f & 15) << 2;
            *(float4*)(Bs + t * Q + kp) = *(const float4*)(g_fw + (size_t)(5120 + ch * 64 + t) * 64 + kp);
        }
#pragma unroll
        for (int q = 0; q < 16; ++q) {
            int idx = q * 256 + tid, n = idx & 63, t = idx >> 6;
            int j2 = ch * 64 + t, u = j2 >> 4, v = j2 & 15;
            const float* xu_ = xsT + (96 + u * 5) * Q + n;
            const float* xv_ = xsT + (96 + v * 5) * Q + n;
            float s = xu_[0] * xv_[0] + xu_[Q] * xv_[Q] + xu_[2 * Q] * xv_[2 * Q]
                    + xu_[3 * Q] * xv_[3 * Q] + xu_[4 * Q] * xv_[4 * Q];
            AT[t * Q + n] = s;
        }
        __syncthreads();
#pragma unroll 8
        for (int kk = 0; kk < 64; ++kk) {
            ulonglong2 a = *(const ulonglong2*)(AT + kk * Q + r0);
            float4 b = *(const float4*)(Bs + kk * Q + c0);
            MM44P(a, b);
        }
        __syncthreads();
    }
    UNPACKP;
#pragma unroll
    for (int i = 0; i < 4; ++i) {
        int n = bn + r0 + i;
        if (n < NROWS)
            *(float4*)(g_h2 + (size_t)n * 64 + c0) =
                make_float4(acc[i][0], acc[i][1], acc[i][2], acc[i][3]);
    }
}

__global__ void __launch_bounds__(256, 2) k1ab_fwd(const float* __restrict__ X) {
    extern __shared__ float sm[];
    if (blockIdx.x < NB128) k1a_body(X, sm, blockIdx.x);
    else                    k1b_body(X, sm, blockIdx.x - NB128);
}

// ---------------- K2: MLP fwd+bwd, PERSISTENT (R14-proven) ----------------
#define K2_SMEM ((10 * 64 * Q + 64) * 4)
__global__ void __launch_bounds__(512) k2_mlp(const float* __restrict__ A1, const float* __restrict__ b1,
                                              const float* __restrict__ A2, const float* __restrict__ b2,
                                              const float* __restrict__ A3, const float* __restrict__ b3,
                                              float* __restrict__ Xout) {
    extern __shared__ float sm[];
    float* A1T = sm;
    float* A2T = sm + 64 * Q;
    float* A3T = sm + 2 * 64 * Q;
    float* A1s = sm + 3 * 64 * Q;
    float* A2s = sm + 4 * 64 * Q;
    float* hT  = sm + 5 * 64 * Q;
    float* g1T = sm + 6 * 64 * Q;
    float* d1T = sm + 7 * 64 * Q;
    float* g2T = sm + 8 * 64 * Q;
    float* d2T = sm + 9 * 64 * Q;
    float* s3  = sm + 10 * 64 * Q;
    const int tid = threadIdx.x;

    for (int i = tid; i < 4096; i += 512) {
        int o = i >> 6, c = i & 63;
        float w1 = A1[i], w2 = A2[i], w3 = A3[i];
        A1s[o * Q + c] = w1; A2s[o * Q + c] = w2;
        A1T[c * Q + o] = w1; A2T[c * Q + o] = w2; A3T[c * Q + o] = w3;
    }
    __syncthreads();
    if (tid < 64) {
        float s = 0.f;
        for (int k = 0; k < 64; ++k) s += A3T[tid * Q + k];
        s3[tid] = s;
    }
    __syncthreads();

    const int cg = tid & 15, rg = tid >> 4, o0 = cg * 4, n0 = rg * 2;
    float rb1[4], rb2[4], rb3[4], rs3[4];
#pragma unroll
    for (int j = 0; j < 4; ++j) {
        rb1[j] = b1[o0 + j]; rb2[j] = b2[o0 + j]; rb3[j] = b3[o0 + j];
        rs3[j] = s3[o0 + j];
    }

    u64 accp[4];
    float zlo[4], zhi[4];
#define K2GEMM(SRC, WT) { \
    accp[0] = accp[1] = accp[2] = accp[3] = 0ULL; \
    _Pragma("unroll 8") \
    for (int kk = 0; kk < 64; ++kk) { \
        u64 a = *(const u64*)(SRC + kk * Q + n0); \
        float4 b = *(const float4*)(WT + kk * Q + o0); \
        fma2(accp[0], a, pk2(b.x, b.x)); fma2(accp[1], a, pk2(b.y, b.y)); \
        fma2(accp[2], a, pk2(b.z, b.z)); fma2(accp[3], a, pk2(b.w, b.w)); \
    } \
    _Pragma("unroll") \
    for (int j = 0; j < 4; ++j) upk2(accp[j], zlo[j], zhi[j]); }

    for (int tile = blockIdx.x; tile < NB64; tile += K2_GRID) {
        const int bn = tile * 64;
        for (int i = tid; i < 4096; i += 512) {
            int n = i >> 6, c = i & 63;
            hT[c * Q + n] = (bn + n < NROWS)
                ? g_h[(size_t)(bn + n) * 64 + c] + g_h2[(size_t)(bn + n) * 64 + c] : 0.f;
        }
        __syncthreads();

        K2GEMM(hT, A1T);
#pragma unroll
        for (int j = 0; j < 4; ++j) {
            float za = zlo[j] + rb1[j], zb = zhi[j] + rb1[j];
            float sa = 1.f / (1.f + expf(-za)), sb = 1.f / (1.f + expf(-zb));
            *(float2*)(g1T + (o0 + j) * Q + n0) = make_float2(za * sa, zb * sb);
            *(float2*)(d1T + (o0 + j) * Q + n0) =
                make_float2(sa * (1.f + za * (1.f - sa)), sb * (1.f + zb * (1.f - sb)));
        }
        __syncthreads();
        K2GEMM(g1T, A2T);
#pragma unroll
        for (int j = 0; j < 4; ++j) {
            float za = zlo[j] + rb2[j], zb = zhi[j] + rb2[j];
            float sa = 1.f / (1.f + expf(-za)), sb = 1.f / (1.f + expf(-zb));
            *(float2*)(g2T + (o0 + j) * Q + n0) = make_float2(za * sa, zb * sb);
            *(float2*)(d2T + (o0 + j) * Q + n0) =
                make_float2(rs3[j] * sa * (1.f + za * (1.f - sa)),
                            rs3[j] * sb * (1.f + zb * (1.f - sb)));
        }
        __syncthreads();
        K2GEMM(g2T, A3T);
        if (bn + n0 < NROWS) {
            float4 va = make_float4(zlo[0] + rb3[0], zlo[1] + rb3[1], zlo[2] + rb3[2], zlo[3] + rb3[3]);
            float4 vb = make_float4(zhi[0] + rb3[0], zhi[1] + rb3[1], zhi[2] + rb3[2], zhi[3] + rb3[3]);
            *(float4*)(Xout + (size_t)(bn + n0) * 64 + o0) = va;
            *(float4*)(Xout + (size_t)(bn + n0 + 1) * 64 + o0) = vb;
        }
        K2GEMM(d2T, A2s);
        __syncthreads();
#pragma unroll
        for (int j = 0; j < 4; ++j) {
            float2 d = *(const float2*)(d1T + (o0 + j) * Q + n0);
            *(float2*)(g1T + (o0 + j) * Q + n0) = make_float2(zlo[j] * d.x, zhi[j] * d.y);
        }
        __syncthreads();
        K2GEMM(g1T, A1s);
        if (bn + n0 < NROWS) {
            *(float4*)(g_dh + (size_t)(bn + n0) * 64 + o0) = make_float4(zlo[0], zlo[1], zlo[2], zlo[3]);
            *(float4*)(g_dh + (size_t)(bn + n0 + 1) * 64 + o0) = make_float4(zhi[0], zhi[1], zhi[2], zhi[3]);
        }
        __syncthreads();
    }
#undef K2GEMM
}

// ---------------- K3 bodies ----------------
#define K3A_BYTES ((2 * 64 * P2 + 2 * 64 * Q) * 4)
#define K3B_BYTES ((176 * Q + 64 * Q + 64 * Q + 64 * Q) * 4)
#define K3AB_SMEM (K3A_BYTES > K3B_BYTES ? K3A_BYTES : K3B_BYTES)

// k3a: SYMMETRIC full-merge — one v-loop, A loaded once, p0/p1 pure PSTEP, fold after
__device__ void k3a_body(const float* __restrict__ X, float* __restrict__ out,
                         float* sm, int tile) {
    float* xsT = sm;                 // [64 v][P2] -> n
    float* dhT = sm + 64 * P2;       // [64 k][P2] -> n
    float* Bs  = sm + 128 * P2;      // [2][64][Q]
    const int tid = threadIdx.x, bn = tile * 128;

    for (int i = tid; i < 8192; i += 256) {
        int n = i >> 6, c = i & 63;
        bool ok = (bn + n) < NROWS;
        xsT[c * P2 + n] = ok ? X[(size_t)(bn + n) * 240 + c] : 0.f;
        dhT[c * P2 + n] = ok ? g_dh[(size_t)(bn + n) * 64 + c] : 0.f;
    }
    __syncthreads();
    const int cg = tid & 15, rg = tid >> 4;
    const int r0 = rg * 8, c0 = cg * 4;
    u64 acc[4][4];
#pragma unroll
    for (int i = 0; i < 4; i++)
#pragma unroll
        for (int j = 0; j < 4; j++) acc[i][j] = 0ULL;

    for (int ch0 = 0; ch0 < 64; ch0 += 2) {
#pragma unroll
        for (int q = 0; q < 8; ++q) {
            int f = tid + 256 * q;
            int buf = f >> 10, t = (f >> 4) & 63, kp = (f & 15) << 2;
            *(float4*)(Bs + buf * 64 * Q + t * Q + kp) =
                *(const float4*)(g_bw + (size_t)((ch0 + buf) * 64 + t) * 64 + kp);
        }
        __syncthreads();
        u64 p0[4][4], p1[4][4]; ZP(p0); ZP(p1);
#pragma unroll 2
        for (int v = 0; v < 64; ++v) {
            ulonglong2 a01 = *(const ulonglong2*)(xsT + v * P2 + r0);
            ulonglong2 a23 = *(const ulonglong2*)(xsT + v * P2 + r0 + 4);
            float4 b0 = *(const float4*)(Bs + v * Q + c0);
            float4 b1 = *(const float4*)(Bs + 64 * Q + v * Q + c0);
            PSTEP(p0, b0);
            PSTEP(p1, b1);
        }
        {
            ulonglong2 dp = *(const ulonglong2*)(dhT + ch0 * P2 + r0);
            ulonglong2 dq = *(const ulonglong2*)(dhT + ch0 * P2 + r0 + 4);
            u64 f0[4] = {dp.x, dp.y, dq.x, dq.y};
            PFOLD(p0, f0);
        }
        {
            ulonglong2 dp = *(const ulonglong2*)(dhT + (ch0 + 1) * P2 + r0);
            ulonglong2 dq = *(const ulonglong2*)(dhT + (ch0 + 1) * P2 + r0 + 4);
            u64 f1[4] = {dp.x, dp.y, dq.x, dq.y};
            PFOLD(p1, f1);
        }
        __syncthreads();
    }
    if (bn + r0 < NROWS) {
#pragma unroll
        for (int i2 = 0; i2 < 4; ++i2) {
            float4 va, vb;
            upk2(acc[i2][0], va.x, vb.x); upk2(acc[i2][1], va.y, vb.y);
            upk2(acc[i2][2], va.z, vb.z); upk2(acc[i2][3], va.w, vb.w);
            size_t na = (size_t)(bn + r0 + 2 * i2);
            *(float4*)(out + XOFF + na * 240 + c0) = va;
            *(float4*)(out + XOFF + (na + 1) * 240 + c0) = vb;
        }
    }
}

__device__ void k3b_body(const float* __restrict__ X, float* __restrict__ out,
                         float* sm, int tile) {
    float* xsT = sm;
    float* dhT = sm + 176 * Q;
    float* Bs  = sm + 240 * Q;
    float* Gs  = sm + 304 * Q;
    const int tid = threadIdx.x, bn = tile * 64;

    for (int i = tid; i < 176 * 64; i += 256) {
        int n = i / 176, c = i - n * 176;
        xsT[c * Q + n] = (bn + n < NROWS) ? X[(size_t)(bn + n) * 240 + 64 + c] : 0.f;
    }
    for (int i = tid; i < 4096; i += 256) {
        int n = i >> 6, c = i & 63;
        dhT[c * Q + n] = (bn + n < NROWS) ? g_dh[(size_t)(bn + n) * 64 + c] : 0.f;
    }
    __syncthreads();
    const int cg = tid & 15, rg = tid >> 4, r0 = rg * 4, c0 = cg * 4;
    const int an = tid & 63, ag = tid >> 6;
    u64 accp[2][4];
    float acc[4][4];

    {
        float y1[8][3];
#pragma unroll
        for (int a = 0; a < 8; a++)
#pragma unroll
            for (int m = 0; m < 3; m++) y1[a][m] = 0.f;
        for (int ch = 0; ch < 16; ++ch) {
#pragma unroll
            for (int q = 0; q < 4; ++q) {
                int f = tid + 256 * q, t = f >> 4, wp = (f & 15) << 2;
                *(float4*)(Bs + t * Q + wp) =
                    *(const float4*)(g_bw + BW1_OFF + (size_t)t * 1024 + ch * 64 + wp);
            }
            __syncthreads();
            ZACCP;
#pragma unroll 8
            for (int kk = 0; kk < 64; ++kk) {
                ulonglong2 a = *(const ulonglong2*)(dhT + kk * Q + r0);
                float4 b = *(const float4*)(Bs + kk * Q + c0);
                MM44P(a, b);
            }
            UNPACKP;
#pragma unroll
            for (int j = 0; j < 4; ++j)
                *(float4*)(Gs + (c0 + j) * Q + r0) =
                    make_float4(acc[0][j], acc[1][j], acc[2][j], acc[3][j]);
            __syncthreads();
            float xa[3], xb[3];
#pragma unroll
            for (int m = 0; m < 3; m++) {
                xa[m] = xsT[((2 * ch) * 3 + m) * Q + an];
                xb[m] = xsT[((2 * ch + 1) * 3 + m) * Q + an];
            }
#pragma unroll
            for (int ww = 0; ww < 8; ++ww) {
                int w = ag * 8 + ww;
                float g0 = Gs[w * Q + an];
                float g1 = Gs[(32 + w) * Q + an];
#pragma unroll
                for (int m = 0; m < 3; m++) y1[ww][m] += g0 * xa[m] + g1 * xb[m];
            }
            __syncthreads();
        }
        if (bn + an < NROWS) {
#pragma unroll
            for (int ww = 0; ww < 8; ++ww)
#pragma unroll
                for (int m = 0; m < 3; m++)
                    out[XOFF + (size_t)(bn + an) * 240 + 64 + (ag * 8 + ww) * 3 + m] = y1[ww][m];
        }
    }
    {
        float y2[4][5];
#pragma unroll
        for (int a = 0; a < 4; a++)
#pragma unroll
            for (int m = 0; m < 5; m++) y2[a][m] = 0.f;
        for (int ch = 0; ch < 4; ++ch) {
#pragma unroll
            for (int q = 0; q < 4; ++q) {
                int f = tid + 256 * q, t = f >> 4, wp = (f & 15) << 2;
                *(float4*)(Bs + t * Q + wp) =
                    *(const float4*)(g_bw + BW2_OFF + (size_t)t * 256 + ch * 64 + wp);
            }
            __syncthreads();
            ZACCP;
#pragma unroll 8
            for (int kk = 0; kk < 64; ++kk) {
                ulonglong2 a = *(const ulonglong2*)(dhT + kk * Q + r0);
                float4 b = *(const float4*)(Bs + kk * Q + c0);
                MM44P(a, b);
            }
            UNPACKP;
#pragma unroll
            for (int j = 0; j < 4; ++j)
                *(float4*)(Gs + (c0 + j) * Q + r0) =
                    make_float4(acc[0][j], acc[1][j], acc[2][j], acc[3][j]);
            __syncthreads();
            float xv[4][5];
#pragma unroll
            for (int vv = 0; vv < 4; vv++)
#pragma unroll
                for (int m = 0; m < 5; m++)
                    xv[vv][m] = xsT[(96 + (4 * ch + vv) * 5 + m) * Q + an];
#pragma unroll
            for (int ww = 0; ww < 4; ++ww) {
                int w = ag * 4 + ww;
#pragma unroll
                for (int vv = 0; vv < 4; vv++) {
                    float g = Gs[(vv * 16 + w) * Q + an];
#pragma unroll
                    for (int m = 0; m < 5; m++) y2[ww][m] += g * xv[vv][m];
                }
            }
            __syncthreads();
        }
        if (bn + an < NROWS) {
#pragma unroll
            for (int ww = 0; ww < 4; ++ww)
#pragma unroll
                for (int m = 0; m < 5; m++)
                    out[XOFF + (size_t)(bn + an) * 240 + 160 + (ag * 4 + ww) * 5 + m] = y2[ww][m];
        }
    }
}

__global__ void __launch_bounds__(256, 2) k3ab_bwd(const float* __restrict__ X,
                                                   float* __restrict__ out) {
    extern __shared__ float sm[];
    if (blockIdx.x < NB128) k3a_body(X, out, sm, blockIdx.x);
    else                    k3b_body(X, out, sm, blockIdx.x - NB128);
}

// ---------------- launch ----------------
extern "C" void kernel_launch(void* const* d_in, const int* in_sizes, int n_in,
                              void* d_out, int out_size) {
    const float* X  = (const float*)d_in[0];
    const float* W0 = (const float*)d_in[1];
    const float* W1 = (const float*)d_in[2];
    const float* W2 = (const float*)d_in[3];
    const float* A1 = (const float*)d_in[4];
    const float* b1 = (const float*)d_in[5];
    const float* A2 = (const float*)d_in[6];
    const float* b2 = (const float*)d_in[7];
    const float* A3 = (const float*)d_in[8];
    const float* b3 = (const float*)d_in[9];
    float* out = (float*)d_out;

    cudaFuncSetAttribute(k1ab_fwd, cudaFuncAttributeMaxDynamicSharedMemorySize, K1AB_SMEM);
    cudaFuncSetAttribute(k2_mlp,   cudaFuncAttributeMaxDynamicSharedMemorySize, K2_SMEM);
    cudaFuncSetAttribute(k3ab_bwd, cudaFuncAttributeMaxDynamicSharedMemorySize, K3AB_SMEM);

    prep_w<<<(FW_TOT + BW_TOT + 255) / 256, 256>>>(W0, W1, W2);
    k1ab_fwd<<<NB128 + NB64, 256, K1AB_SMEM>>>(X);
    k2_mlp<<<K2_GRID, 512, K2_SMEM>>>(A1, b1, A2, b2, A3, b3, out);
    k3ab_bwd<<<NB128 + NB64, 256, K3AB_SMEM>>>(X, out);
}

// round 17
// speedup vs baseline: 1.0592x; 1.0212x over previous
#include <cuda_runtime.h>

#define NROWS 50000
#define NB64  782
#define NB128 391
#define XOFF  (NROWS * 64)
#define BW1_OFF (64 * 64 * 64)
#define BW2_OFF (BW1_OFF + 64 * 1024)
#define BW_TOT  (BW2_OFF + 64 * 256)
#define FW_TOT  (5376 * 64)
#define Q 68
#define P2 132
#define K2_GRID 152

typedef unsigned long long u64;
__device__ __forceinline__ u64 pk2(float lo, float hi) {
    u64 r; asm("mov.b64 %0,{%1,%2};" : "=l"(r) : "f"(lo), "f"(hi)); return r;
}
__device__ __forceinline__ void fma2(u64& d, u64 a, u64 b) {
    asm("fma.rn.f32x2 %0,%1,%2,%0;" : "+l"(d) : "l"(a), "l"(b));
}
__device__ __forceinline__ void upk2(u64 v, float& lo, float& hi) {
    asm("mov.b64 {%0,%1},%2;" : "=f"(lo), "=f"(hi) : "l"(v));
}

__device__ __align__(16) float g_h [NB64 * 64 * 64];
__device__ __align__(16) float g_h2[NB64 * 64 * 64];
__device__ __align__(16) float g_dh[NB64 * 64 * 64];
__device__ __align__(16) float g_fw[FW_TOT];
__device__ __align__(16) float g_bw[BW_TOT];

#define MM44P(aul, b4) { \
    u64 bb; \
    bb = pk2(b4.x,b4.x); fma2(accp[0][0],aul.x,bb); fma2(accp[1][0],aul.y,bb); \
    bb = pk2(b4.y,b4.y); fma2(accp[0][1],aul.x,bb); fma2(accp[1][1],aul.y,bb); \
    bb = pk2(b4.z,b4.z); fma2(accp[0][2],aul.x,bb); fma2(accp[1][2],aul.y,bb); \
    bb = pk2(b4.w,b4.w); fma2(accp[0][3],aul.x,bb); fma2(accp[1][3],aul.y,bb); }
#define ZACCP  { for (int i_=0;i_<2;i_++) for (int j_=0;j_<4;j_++) accp[i_][j_]=0ULL; }
#define UNPACKP { for (int i_=0;i_<2;i_++) for (int j_=0;j_<4;j_++) upk2(accp[i_][j_], acc[2*i_][j_], acc[2*i_+1][j_]); }

// pure packed GEMM step into p (8 rows x 4 cols)
#define PSTEP(pp, b4) { \
    u64 bb; \
    bb = pk2(b4.x,b4.x); fma2(pp[0][0],a01.x,bb); fma2(pp[1][0],a01.y,bb); fma2(pp[2][0],a23.x,bb); fma2(pp[3][0],a23.y,bb); \
    bb = pk2(b4.y,b4.y); fma2(pp[0][1],a01.x,bb); fma2(pp[1][1],a01.y,bb); fma2(pp[2][1],a23.x,bb); fma2(pp[3][1],a23.y,bb); \
    bb = pk2(b4.z,b4.z); fma2(pp[0][2],a01.x,bb); fma2(pp[1][2],a01.y,bb); fma2(pp[2][2],a23.x,bb); fma2(pp[3][2],a23.y,bb); \
    bb = pk2(b4.w,b4.w); fma2(pp[0][3],a01.x,bb); fma2(pp[1][3],a01.y,bb); fma2(pp[2][3],a23.x,bb); fma2(pp[3][3],a23.y,bb); }
#define ZP(pp)  { for (int i_=0;i_<4;i_++) for (int j_=0;j_<4;j_++) pp[i_][j_]=0ULL; }
#define PFOLD(pp, f) { for (int i_=0;i_<4;i_++) for (int j_=0;j_<4;j_++) fma2(acc[i_][j_], pp[i_][j_], f[i_]); }

// ---------------- prep ----------------
__global__ void prep_w(const float* __restrict__ W0, const float* __restrict__ W1,
                       const float* __restrict__ W2) {
    const float C0 = rsqrtf(5376.0f);
    const float C1 = C0 * rsqrtf(3.0f);
    const float C2 = C0 * rsqrtf(5.0f);
    int idx = blockIdx.x * blockDim.x + threadIdx.x;
    if (idx < FW_TOT) {
        int j = idx >> 6, k = idx & 63;
        float v_;
        if (j < 4096) {
            int u = j >> 6, v = j & 63;
            if (u < v)       v_ = C0 * (W0[(u*64+v)*64+k] + W0[(v*64+u)*64+k]);
            else if (u == v) v_ = C0 * W0[(u*64+u)*64+k];
            else             v_ = 0.f;
        } else if (j < 5120) {
            int t = j - 4096, u = t >> 5, v = t & 31;
            v_ = 0.5f * C1 * (W1[(u*32+v)*64+k] + W1[(v*32+u)*64+k]);
        } else {
            int t = j - 5120, u = t >> 4, v = t & 15;
            v_ = 0.5f * C2 * (W2[(u*16+v)*64+k] + W2[(v*16+u)*64+k]);
        }
        g_fw[idx] = v_;
    } else if (idx < FW_TOT + BW_TOT) {
        int i = idx - FW_TOT;
        float v_;
        if (i < BW1_OFF) {
            int w = i & 63, r = i >> 6, k = r >> 6, v = r & 63;
            v_ = C0 * (W0[(v*64+w)*64+k] + W0[(w*64+v)*64+k]);
        } else if (i < BW2_OFF) {
            int t = i - BW1_OFF, w = t & 31, r = t >> 5, k = r >> 5, v = r & 31;
            v_ = C1 * (W1[(v*32+w)*64+k] + W1[(w*32+v)*64+k]);
        } else {
            int t = i - BW2_OFF, w = t & 15, r = t >> 4, k = r >> 4, v = r & 15;
            v_ = C2 * (W2[(v*16+w)*64+k] + W2[(w*16+v)*64+k]);
        }
        g_bw[i] = v_;
    }
}

// ---------------- K1 bodies ----------------
#define K1A_BYTES ((64 * P2 + 2 * 64 * Q) * 4)
#define K1B_BYTES ((176 * Q + 64 * Q + 64 * Q) * 4)
#define K1AB_SMEM (K1B_BYTES > K1A_BYTES ? K1B_BYTES : K1A_BYTES)

__device__ void k1a_body(const float* __restrict__ X, float* sm, int tile) {
    float* xsT = sm;               // [64 c][P2] -> n
    float* Bs  = sm + 64 * P2;     // [2][64][Q]
    const int tid = threadIdx.x, bn = tile * 128;

    for (int i = tid; i < 8192; i += 256) {
        int n = i >> 6, c = i & 63;
        xsT[c * P2 + n] = (bn + n < NROWS) ? X[(size_t)(bn + n) * 240 + c] : 0.f;
    }
    __syncthreads();
    const int cg = tid & 15, rg = tid >> 4;
    const int r0 = rg * 8, c0 = cg * 4;
    u64 acc[4][4];
#pragma unroll
    for (int i = 0; i < 4; i++)
#pragma unroll
        for (int j = 0; j < 4; j++) acc[i][j] = 0ULL;

    for (int u0 = 0; u0 < 64; u0 += 2) {
#pragma unroll
        for (int q = 0; q < 8; ++q) {
            int f = tid + 256 * q;
            int buf = f >> 10, t = (f >> 4) & 63, kp = (f & 15) << 2;
            if (t >= u0 + buf)
                *(float4*)(Bs + buf * 64 * Q + t * Q + kp) =
                    *(const float4*)(g_fw + (size_t)((u0 + buf) * 64 + t) * 64 + kp);
        }
        __syncthreads();
        {
            u64 p[4][4]; ZP(p);
#pragma unroll 4
            for (int v = u0; v < 64; ++v) {
                ulonglong2 a01 = *(const ulonglong2*)(xsT + v * P2 + r0);
                ulonglong2 a23 = *(const ulonglong2*)(xsT + v * P2 + r0 + 4);
                float4 b = *(const float4*)(Bs + v * Q + c0);
                PSTEP(p, b);
            }
            ulonglong2 xp = *(const ulonglong2*)(xsT + u0 * P2 + r0);
            ulonglong2 xq = *(const ulonglong2*)(xsT + u0 * P2 + r0 + 4);
            u64 f0[4] = {xp.x, xp.y, xq.x, xq.y};
            PFOLD(p, f0);
        }
        {
            u64 p[4][4]; ZP(p);
#pragma unroll 4
            for (int v = u0 + 1; v < 64; ++v) {
                ulonglong2 a01 = *(const ulonglong2*)(xsT + v * P2 + r0);
                ulonglong2 a23 = *(const ulonglong2*)(xsT + v * P2 + r0 + 4);
                float4 b = *(const float4*)(Bs + 64 * Q + v * Q + c0);
                PSTEP(p, b);
            }
            ulonglong2 xp = *(const ulonglong2*)(xsT + (u0 + 1) * P2 + r0);
            ulonglong2 xq = *(const ulonglong2*)(xsT + (u0 + 1) * P2 + r0 + 4);
            u64 f1[4] = {xp.x, xp.y, xq.x, xq.y};
            PFOLD(p, f1);
        }
        __syncthreads();
    }
    if (bn + r0 < NROWS) {
#pragma unroll
        for (int i2 = 0; i2 < 4; ++i2) {
            float4 va, vb;
            upk2(acc[i2][0], va.x, vb.x); upk2(acc[i2][1], va.y, vb.y);
            upk2(acc[i2][2], va.z, vb.z); upk2(acc[i2][3], va.w, vb.w);
            size_t na = (size_t)(bn + r0 + 2 * i2);
            *(float4*)(g_h + na * 64 + c0) = va;
            *(float4*)(g_h + (na + 1) * 64 + c0) = vb;
        }
    }
}

__device__ void k1b_body(const float* __restrict__ X, float* sm, int tile) {
    float* xsT = sm;               // [176 c][Q] -> n  (X cols 64..239)
    float* AT  = sm + 176 * Q;
    float* Bs  = sm + 240 * Q;
    const int tid = threadIdx.x, bn = tile * 64;

    for (int i = tid; i < 176 * 64; i += 256) {
        int n = i / 176, c = i - n * 176;
        xsT[c * Q + n] = (bn + n < NROWS) ? X[(size_t)(bn + n) * 240 + 64 + c] : 0.f;
    }
    __syncthreads();
    const int cg = tid & 15, rg = tid >> 4, r0 = rg * 4, c0 = cg * 4;
    u64 accp[2][4]; ZACCP;
    float acc[4][4];

    for (int ch = 0; ch < 16; ++ch) {
#pragma unroll
        for (int q = 0; q < 4; ++q) {
            int f = tid + 256 * q, t = f >> 4, kp = (f & 15) << 2;
            *(float4*)(Bs + t * Q + kp) = *(const float4*)(g_fw + (size_t)(4096 + ch * 64 + t) * 64 + kp);
        }
#pragma unroll
        for (int q = 0; q < 16; ++q) {
            int idx = q * 256 + tid, n = idx & 63, t = idx >> 6;
            int j1 = ch * 64 + t, u = j1 >> 5, v = j1 & 31;
            const float* xu_ = xsT + (u * 3) * Q + n;
            const float* xv_ = xsT + (v * 3) * Q + n;
            AT[t * Q + n] = xu_[0] * xv_[0] + xu_[Q] * xv_[Q] + xu_[2 * Q] * xv_[2 * Q];
        }
        __syncthreads();
#pragma unroll 8
        for (int kk = 0; kk < 64; ++kk) {
            ulonglong2 a = *(const ulonglong2*)(AT + kk * Q + r0);
            float4 b = *(const float4*)(Bs + kk * Q + c0);
            MM44P(a, b);
        }
        __syncthreads();
    }
    for (int ch = 0; ch < 4; ++ch) {
#pragma unroll
        for (int q = 0; q < 4; ++q) {
            int f = tid + 256 * q, t = f >> 4, kp = (f & 15) << 2;
            *(float4*)(Bs + t * Q + kp) = *(const float4*)(g_fw + (size_t)(5120 + ch * 64 + t) * 64 + kp);
        }
#pragma unroll
        for (int q = 0; q < 16; ++q) {
            int idx = q * 256 + tid, n = idx & 63, t = idx >> 6;
            int j2 = ch * 64 + t, u = j2 >> 4, v = j2 & 15;
            const float* xu_ = xsT + (96 + u * 5) * Q + n;
            const float* xv_ = xsT + (96 + v * 5) * Q + n;
            float s = xu_[0] * xv_[0] + xu_[Q] * xv_[Q] + xu_[2 * Q] * xv_[2 * Q]
                    + xu_[3 * Q] * xv_[3 * Q] + xu_[4 * Q] * xv_[4 * Q];
            AT[t * Q + n] = s;
        }
        __syncthreads();
#pragma unroll 8
        for (int kk = 0; kk < 64; ++kk) {
            ulonglong2 a = *(const ulonglong2*)(AT + kk * Q + r0);
            float4 b = *(const float4*)(Bs + kk * Q + c0);
            MM44P(a, b);
        }
        __syncthreads();
    }
    UNPACKP;
#pragma unroll
    for (int i = 0; i < 4; ++i) {
        int n = bn + r0 + i;
        if (n < NROWS)
            *(float4*)(g_h2 + (size_t)n * 64 + c0) =
                make_float4(acc[i][0], acc[i][1], acc[i][2], acc[i][3]);
    }
}

// sequential block ranges: a-blocks first, b-blocks backfill the tail
__global__ void __launch_bounds__(256, 2) k1ab_fwd(const float* __restrict__ X) {
    extern __shared__ float sm[];
    if (blockIdx.x < NB128) k1a_body(X, sm, blockIdx.x);
    else                    k1b_body(X, sm, blockIdx.x - NB128);
}

// ---------------- K2: MLP fwd+bwd, PERSISTENT ----------------
#define K2_SMEM ((10 * 64 * Q + 64) * 4)
__global__ void __launch_bounds__(512) k2_mlp(const float* __restrict__ A1, const float* __restrict__ b1,
                                              const float* __restrict__ A2, const float* __restrict__ b2,
                                              const float* __restrict__ A3, const float* __restrict__ b3,
                                              float* __restrict__ Xout) {
    extern __shared__ float sm[];
    float* A1T = sm;
    float* A2T = sm + 64 * Q;
    float* A3T = sm + 2 * 64 * Q;
    float* A1s = sm + 3 * 64 * Q;
    float* A2s = sm + 4 * 64 * Q;
    float* hT  = sm + 5 * 64 * Q;
    float* g1T = sm + 6 * 64 * Q;
    float* d1T = sm + 7 * 64 * Q;
    float* g2T = sm + 8 * 64 * Q;
    float* d2T = sm + 9 * 64 * Q;
    float* s3  = sm + 10 * 64 * Q;
    const int tid = threadIdx.x;

    for (int i = tid; i < 4096; i += 512) {
        int o = i >> 6, c = i & 63;
        float w1 = A1[i], w2 = A2[i], w3 = A3[i];
        A1s[o * Q + c] = w1; A2s[o * Q + c] = w2;
        A1T[c * Q + o] = w1; A2T[c * Q + o] = w2; A3T[c * Q + o] = w3;
    }
    __syncthreads();
    if (tid < 64) {
        float s = 0.f;
        for (int k = 0; k < 64; ++k) s += A3T[tid * Q + k];
        s3[tid] = s;
    }
    __syncthreads();

    const int cg = tid & 15, rg = tid >> 4, o0 = cg * 4, n0 = rg * 2;
    float rb1[4], rb2[4], rb3[4], rs3[4];
#pragma unroll
    for (int j = 0; j < 4; ++j) {
        rb1[j] = b1[o0 + j]; rb2[j] = b2[o0 + j]; rb3[j] = b3[o0 + j];
        rs3[j] = s3[o0 + j];
    }

    u64 accp[4];
    float zlo[4], zhi[4];
#define K2GEMM(SRC, WT) { \
    accp[0] = accp[1] = accp[2] = accp[3] = 0ULL; \
    _Pragma("unroll 8") \
    for (int kk = 0; kk < 64; ++kk) { \
        u64 a = *(const u64*)(SRC + kk * Q + n0); \
        float4 b = *(const float4*)(WT + kk * Q + o0); \
        fma2(accp[0], a, pk2(b.x, b.x)); fma2(accp[1], a, pk2(b.y, b.y)); \
        fma2(accp[2], a, pk2(b.z, b.z)); fma2(accp[3], a, pk2(b.w, b.w)); \
    } \
    _Pragma("unroll") \
    for (int j = 0; j < 4; ++j) upk2(accp[j], zlo[j], zhi[j]); }

    for (int tile = blockIdx.x; tile < NB64; tile += K2_GRID) {
        const int bn = tile * 64;
        for (int i = tid; i < 4096; i += 512) {
            int n = i >> 6, c = i & 63;
            hT[c * Q + n] = (bn + n < NROWS)
                ? g_h[(size_t)(bn + n) * 64 + c] + g_h2[(size_t)(bn + n) * 64 + c] : 0.f;
        }
        __syncthreads();

        K2GEMM(hT, A1T);
#pragma unroll
        for (int j = 0; j < 4; ++j) {
            float za = zlo[j] + rb1[j], zb = zhi[j] + rb1[j];
            float sa = 1.f / (1.f + expf(-za)), sb = 1.f / (1.f + expf(-zb));
            *(float2*)(g1T + (o0 + j) * Q + n0) = make_float2(za * sa, zb * sb);
            *(float2*)(d1T + (o0 + j) * Q + n0) =
                make_float2(sa * (1.f + za * (1.f - sa)), sb * (1.f + zb * (1.f - sb)));
        }
        __syncthreads();
        K2GEMM(g1T, A2T);
#pragma unroll
        for (int j = 0; j < 4; ++j) {
            float za = zlo[j] + rb2[j], zb = zhi[j] + rb2[j];
            float sa = 1.f / (1.f + expf(-za)), sb = 1.f / (1.f + expf(-zb));
            *(float2*)(g2T + (o0 + j) * Q + n0) = make_float2(za * sa, zb * sb);
            *(float2*)(d2T + (o0 + j) * Q + n0) =
                make_float2(rs3[j] * sa * (1.f + za * (1.f - sa)),
                            rs3[j] * sb * (1.f + zb * (1.f - sb)));
        }
        __syncthreads();
        K2GEMM(g2T, A3T);
        if (bn + n0 < NROWS) {
            float4 va = make_float4(zlo[0] + rb3[0], zlo[1] + rb3[1], zlo[2] + rb3[2], zlo[3] + rb3[3]);
            float4 vb = make_float4(zhi[0] + rb3[0], zhi[1] + rb3[1], zhi[2] + rb3[2], zhi[3] + rb3[3]);
            *(float4*)(Xout + (size_t)(bn + n0) * 64 + o0) = va;
            *(float4*)(Xout + (size_t)(bn + n0 + 1) * 64 + o0) = vb;
        }
        K2GEMM(d2T, A2s);
        __syncthreads();
#pragma unroll
        for (int j = 0; j < 4; ++j) {
            float2 d = *(const float2*)(d1T + (o0 + j) * Q + n0);
            *(float2*)(g1T + (o0 + j) * Q + n0) = make_float2(zlo[j] * d.x, zhi[j] * d.y);
        }
        __syncthreads();
        K2GEMM(g1T, A1s);
        if (bn + n0 < NROWS) {
            *(float4*)(g_dh + (size_t)(bn + n0) * 64 + o0) = make_float4(zlo[0], zlo[1], zlo[2], zlo[3]);
            *(float4*)(g_dh + (size_t)(bn + n0 + 1) * 64 + o0) = make_float4(zhi[0], zhi[1], zhi[2], zhi[3]);
        }
        __syncthreads();
    }
#undef K2GEMM
}

// ---------------- K3 bodies ----------------
#define K3A_BYTES ((2 * 64 * P2 + 2 * 64 * Q) * 4)
#define K3B_BYTES ((176 * Q + 64 * Q + 64 * Q + 64 * Q) * 4)
#define K3AB_SMEM (K3A_BYTES > K3B_BYTES ? K3A_BYTES : K3B_BYTES)

__device__ void k3a_body(const float* __restrict__ X, float* __restrict__ out,
                         float* sm, int tile) {
    float* xsT = sm;                 // [64 v][P2] -> n
    float* dhT = sm + 64 * P2;       // [64 k][P2] -> n
    float* Bs  = sm + 128 * P2;      // [2][64][Q]
    const int tid = threadIdx.x, bn = tile * 128;

    for (int i = tid; i < 8192; i += 256) {
        int n = i >> 6, c = i & 63;
        bool ok = (bn + n) < NROWS;
        xsT[c * P2 + n] = ok ? X[(size_t)(bn + n) * 240 + c] : 0.f;
        dhT[c * P2 + n] = ok ? g_dh[(size_t)(bn + n) * 64 + c] : 0.f;
    }
    __syncthreads();
    const int cg = tid & 15, rg = tid >> 4;
    const int r0 = rg * 8, c0 = cg * 4;
    u64 acc[4][4];
#pragma unroll
    for (int i = 0; i < 4; i++)
#pragma unroll
        for (int j = 0; j < 4; j++) acc[i][j] = 0ULL;

    for (int ch0 = 0; ch0 < 64; ch0 += 2) {
#pragma unroll
        for (int q = 0; q < 8; ++q) {
            int f = tid + 256 * q;
            int buf = f >> 10, t = (f >> 4) & 63, kp = (f & 15) << 2;
            *(float4*)(Bs + buf * 64 * Q + t * Q + kp) =
                *(const float4*)(g_bw + (size_t)((ch0 + buf) * 64 + t) * 64 + kp);
        }
        __syncthreads();
        {
            u64 p[4][4]; ZP(p);
#pragma unroll 4
            for (int v = 0; v < 64; ++v) {
                ulonglong2 a01 = *(const ulonglong2*)(xsT + v * P2 + r0);
                ulonglong2 a23 = *(const ulonglong2*)(xsT + v * P2 + r0 + 4);
                float4 b = *(const float4*)(Bs + v * Q + c0);
                PSTEP(p, b);
            }
            ulonglong2 dp = *(const ulonglong2*)(dhT + ch0 * P2 + r0);
            ulonglong2 dq = *(const ulonglong2*)(dhT + ch0 * P2 + r0 + 4);
            u64 f0[4] = {dp.x, dp.y, dq.x, dq.y};
            PFOLD(p, f0);
        }
        {
            u64 p[4][4]; ZP(p);
#pragma unroll 4
            for (int v = 0; v < 64; ++v) {
                ulonglong2 a01 = *(const ulonglong2*)(xsT + v * P2 + r0);
                ulonglong2 a23 = *(const ulonglong2*)(xsT + v * P2 + r0 + 4);
                float4 b = *(const float4*)(Bs + 64 * Q + v * Q + c0);
                PSTEP(p, b);
            }
            ulonglong2 dp = *(const ulonglong2*)(dhT + (ch0 + 1) * P2 + r0);
            ulonglong2 dq = *(const ulonglong2*)(dhT + (ch0 + 1) * P2 + r0 + 4);
            u64 f1[4] = {dp.x, dp.y, dq.x, dq.y};
            PFOLD(p, f1);
        }
        __syncthreads();
    }
    if (bn + r0 < NROWS) {
#pragma unroll
        for (int i2 = 0; i2 < 4; ++i2) {
            float4 va, vb;
            upk2(acc[i2][0], va.x, vb.x); upk2(acc[i2][1], va.y, vb.y);
            upk2(acc[i2][2], va.z, vb.z); upk2(acc[i2][3], va.w, vb.w);
            size_t na = (size_t)(bn + r0 + 2 * i2);
            *(float4*)(out + XOFF + na * 240 + c0) = va;
            *(float4*)(out + XOFF + (na + 1) * 240 + c0) = vb;
        }
    }
}

__device__ void k3b_body(const float* __restrict__ X, float* __restrict__ out,
                         float* sm, int tile) {
    float* xsT = sm;
    float* dhT = sm + 176 * Q;
    float* Bs  = sm + 240 * Q;
    float* Gs  = sm + 304 * Q;
    const int tid = threadIdx.x, bn = tile * 64;

    for (int i = tid; i < 176 * 64; i += 256) {
        int n = i / 176, c = i - n * 176;
        xsT[c * Q + n] = (bn + n < NROWS) ? X[(size_t)(bn + n) * 240 + 64 + c] : 0.f;
    }
    for (int i = tid; i < 4096; i += 256) {
        int n = i >> 6, c = i & 63;
        dhT[c * Q + n] = (bn + n < NROWS) ? g_dh[(size_t)(bn + n) * 64 + c] : 0.f;
    }
    __syncthreads();
    const int cg = tid & 15, rg = tid >> 4, r0 = rg * 4, c0 = cg * 4;
    const int an = tid & 63, ag = tid >> 6;
    u64 accp[2][4];
    float acc[4][4];

    {
        float y1[8][3];
#pragma unroll
        for (int a = 0; a < 8; a++)
#pragma unroll
            for (int m = 0; m < 3; m++) y1[a][m] = 0.f;
        for (int ch = 0; ch < 16; ++ch) {
#pragma unroll
            for (int q = 0; q < 4; ++q) {
                int f = tid + 256 * q, t = f >> 4, wp = (f & 15) << 2;
                *(float4*)(Bs + t * Q + wp) =
                    *(const float4*)(g_bw + BW1_OFF + (size_t)t * 1024 + ch * 64 + wp);
            }
            __syncthreads();
            ZACCP;
#pragma unroll 8
            for (int kk = 0; kk < 64; ++kk) {
                ulonglong2 a = *(const ulonglong2*)(dhT + kk * Q + r0);
                float4 b = *(const float4*)(Bs + kk * Q + c0);
                MM44P(a, b);
            }
            UNPACKP;
#pragma unroll
            for (int j = 0; j < 4; ++j)
                *(float4*)(Gs + (c0 + j) * Q + r0) =
                    make_float4(acc[0][j], acc[1][j], acc[2][j], acc[3][j]);
            __syncthreads();
            float xa[3], xb[3];
#pragma unroll
            for (int m = 0; m < 3; m++) {
                xa[m] = xsT[((2 * ch) * 3 + m) * Q + an];
                xb[m] = xsT[((2 * ch + 1) * 3 + m) * Q + an];
            }
#pragma unroll
            for (int ww = 0; ww < 8; ++ww) {
                int w = ag * 8 + ww;
                float g0 = Gs[w * Q + an];
                float g1 = Gs[(32 + w) * Q + an];
#pragma unroll
                for (int m = 0; m < 3; m++) y1[ww][m] += g0 * xa[m] + g1 * xb[m];
            }
            __syncthreads();
        }
        if (bn + an < NROWS) {
#pragma unroll
            for (int ww = 0; ww < 8; ++ww)
#pragma unroll
                for (int m = 0; m < 3; m++)
                    out[XOFF + (size_t)(bn + an) * 240 + 64 + (ag * 8 + ww) * 3 + m] = y1[ww][m];
        }
    }
    {
        float y2[4][5];
#pragma unroll
        for (int a = 0; a < 4; a++)
#pragma unroll
            for (int m = 0; m < 5; m++) y2[a][m] = 0.f;
        for (int ch = 0; ch < 4; ++ch) {
#pragma unroll
            for (int q = 0; q < 4; ++q) {
                int f = tid + 256 * q, t = f >> 4, wp = (f & 15) << 2;
                *(float4*)(Bs + t * Q + wp) =
                    *(const float4*)(g_bw + BW2_OFF + (size_t)t * 256 + ch * 64 + wp);
            }
            __syncthreads();
            ZACCP;
#pragma unroll 8
            for (int kk = 0; kk < 64; ++kk) {
                ulonglong2 a = *(const ulonglong2*)(dhT + kk * Q + r0);
                float4 b = *(const float4*)(Bs + kk * Q + c0);
                MM44P(a, b);
            }
            UNPACKP;
#pragma unroll
            for (int j = 0; j < 4; ++j)
                *(float4*)(Gs + (c0 + j) * Q + r0) =
                    make_float4(acc[0][j], acc[1][j], acc[2][j], acc[3][j]);
            __syncthreads();
            float xv[4][5];
#pragma unroll
            for (int vv = 0; vv < 4; vv++)
#pragma unroll
                for (int m = 0; m < 5; m++)
                    xv[vv][m] = xsT[(96 + (4 * ch + vv) * 5 + m) * Q + an];
#pragma unroll
            for (int ww = 0; ww < 4; ++ww) {
                int w = ag * 4 + ww;
#pragma unroll
                for (int vv = 0; vv < 4; vv++) {
                    float g = Gs[(vv * 16 + w) * Q + an];
#pragma unroll
                    for (int m = 0; m < 5; m++) y2[ww][m] += g * xv[vv][m];
                }
            }
            __syncthreads();
        }
        if (bn + an < NROWS) {
#pragma unroll
            for (int ww = 0; ww < 4; ++ww)
#pragma unroll
                for (int m = 0; m < 5; m++)
                    out[XOFF + (size_t)(bn + an) * 240 + 160 + (ag * 4 + ww) * 5 + m] = y2[ww][m];
        }
    }
}

__global__ void __launch_bounds__(256, 2) k3ab_bwd(const float* __restrict__ X,
                                                   float* __restrict__ out) {
    extern __shared__ float sm[];
    if (blockIdx.x < NB128) k3a_body(X, out, sm, blockIdx.x);
    else                    k3b_body(X, out, sm, blockIdx.x - NB128);
}

// ---------------- launch ----------------
extern "C" void kernel_launch(void* const* d_in, const int* in_sizes, int n_in,
                              void* d_out, int out_size) {
    const float* X  = (const float*)d_in[0];
    const float* W0 = (const float*)d_in[1];
    const float* W1 = (const float*)d_in[2];
    const float* W2 = (const float*)d_in[3];
    const float* A1 = (const float*)d_in[4];
    const float* b1 = (const float*)d_in[5];
    const float* A2 = (const float*)d_in[6];
    const float* b2 = (const float*)d_in[7];
    const float* A3 = (const float*)d_in[8];
    const float* b3 = (const float*)d_in[9];
    float* out = (float*)d_out;

    cudaFuncSetAttribute(k1ab_fwd, cudaFuncAttributeMaxDynamicSharedMemorySize, K1AB_SMEM);
    cudaFuncSetAttribute(k2_mlp,   cudaFuncAttributeMaxDynamicSharedMemorySize, K2_SMEM);
    cudaFuncSetAttribute(k3ab_bwd, cudaFuncAttributeMaxDynamicSharedMemorySize, K3AB_SMEM);

    prep_w<<<(FW_TOT + BW_TOT + 255) / 256, 256>>>(W0, W1, W2);
    k1ab_fwd<<<NB128 + NB64, 256, K1AB_SMEM>>>(X);
    k2_mlp<<<K2_GRID, 512, K2_SMEM>>>(A1, b1, A2, b2, A3, b3, out);
    k3ab_bwd<<<NB128 + NB64, 256, K3AB_SMEM>>>(X, out);
}